// round 10
// baseline (speedup 1.0000x reference)
#include <cuda_runtime.h>

// Fused 2-layer LSTM, H=6, B=4096, T=1024 — layer-split warp specialization.
//
// Block = 64 threads = 2 warps, covering 4 batch elements:
//   warp 0: layer-0 cells for its 4 batches, step t
//   warp 1: layer-1 cells for the same batches, step t-1 (pipelined)
// h0 flows warp0 -> warp1 through a 2-slot shared-memory ring; one
// __syncthreads() per step. The two layers now run in separate warp contexts,
// so their ~160-cycle dependency chains overlap in hardware instead of being
// serialized by in-order issue within one warp.
//
// Within a warp: 8 lanes per batch element, lane j owns hidden index j (j<6).
// Weights register-resident, packed f32x2; dot products via fma.rn.f32x2.
// Math is identical to the previous passing kernel (rel_err 3e-7).

#define T_STEPS 1024

__device__ __forceinline__ unsigned long long ffma2(unsigned long long a,
                                                    unsigned long long b,
                                                    unsigned long long c) {
    unsigned long long d;
    asm("fma.rn.f32x2 %0, %1, %2, %3;" : "=l"(d) : "l"(a), "l"(b), "l"(c));
    return d;
}

__device__ __forceinline__ unsigned long long pack2(float lo, float hi) {
    unsigned long long r;
    asm("mov.b64 %0, {%1, %2};" : "=l"(r) : "f"(lo), "f"(hi));
    return r;
}

__device__ __forceinline__ void unpack2(unsigned long long v, float& lo, float& hi) {
    asm("mov.b64 {%0, %1}, %2;" : "=f"(lo), "=f"(hi) : "l"(v));
}

__device__ __forceinline__ float sigmoid_f(float x) {
    return __fdividef(1.0f, 1.0f + __expf(-x));
}

__device__ __forceinline__ float tanh_f(float x) {
    return 1.0f - 2.0f * __fdividef(1.0f, 1.0f + __expf(2.0f * x));
}

// One LSTM cell step for this lane's hidden index. in[3]: packed 6-float input,
// hprev[3]: packed previous hidden, c: cell state (in/out). Returns h_j.
__device__ __forceinline__ float cell_step(
    const unsigned long long Wi[4][3], const unsigned long long Wh[4][3],
    const float B[4], const unsigned long long in[3],
    const unsigned long long hprev[3], float& c)
{
    float gv[4];
#pragma unroll
    for (int g = 0; g < 4; g++) {
        unsigned long long acc = pack2(B[g], 0.0f);
        acc = ffma2(Wi[g][0], in[0], acc);
        acc = ffma2(Wi[g][1], in[1], acc);
        acc = ffma2(Wi[g][2], in[2], acc);
        acc = ffma2(Wh[g][0], hprev[0], acc);
        acc = ffma2(Wh[g][1], hprev[1], acc);
        acc = ffma2(Wh[g][2], hprev[2], acc);
        float lo, hi;
        unpack2(acc, lo, hi);
        gv[g] = lo + hi;
    }
    const float ig = sigmoid_f(gv[0]);
    const float fg = sigmoid_f(gv[1]);
    const float gg = tanh_f(gv[2]);
    const float og = sigmoid_f(gv[3]);
    c = fg * c + ig * gg;
    return og * tanh_f(c);
}

// Broadcast lane values 0..5 of each 8-lane group into packed h[3].
__device__ __forceinline__ void bcast8(float v, unsigned long long h[3]) {
    const float e0 = __shfl_sync(0xffffffffu, v, 0, 8);
    const float e1 = __shfl_sync(0xffffffffu, v, 1, 8);
    const float e2 = __shfl_sync(0xffffffffu, v, 2, 8);
    const float e3 = __shfl_sync(0xffffffffu, v, 3, 8);
    const float e4 = __shfl_sync(0xffffffffu, v, 4, 8);
    const float e5 = __shfl_sync(0xffffffffu, v, 5, 8);
    h[0] = pack2(e0, e1);
    h[1] = pack2(e2, e3);
    h[2] = pack2(e4, e5);
}

__global__ __launch_bounds__(64) void lstm2_kernel(
    const float* __restrict__ x,
    const float* __restrict__ wih0, const float* __restrict__ whh0,
    const float* __restrict__ bi0,  const float* __restrict__ bh0,
    const float* __restrict__ wih1, const float* __restrict__ whh1,
    const float* __restrict__ bi1,  const float* __restrict__ bh1,
    float* __restrict__ out)
{
    // 2-slot ring of layer-0 hidden states: [slot][batch-in-block][8 floats]
    // Row stride 8 floats (32B) keeps the 3 packed-pair loads 8B-aligned.
    __shared__ float h0buf[2][4][8];

    const int warp = threadIdx.x >> 5;     // 0: layer-0 producer, 1: layer-1 consumer
    const int lane = threadIdx.x & 31;
    const int bg   = lane >> 3;            // batch element within block (0..3)
    const int b    = blockIdx.x * 4 + bg;  // global batch element
    const int j    = lane & 7;             // hidden index role
    const bool active = (j < 6);

    // ---- Register-resident weights for THIS warp's layer (packed f32x2).
    const float* wih = (warp == 0) ? wih0 : wih1;
    const float* whh = (warp == 0) ? whh0 : whh1;
    const float* bi  = (warp == 0) ? bi0  : bi1;
    const float* bh  = (warp == 0) ? bh0  : bh1;

    unsigned long long Wi[4][3], Wh[4][3];
    float B[4];
    const int jj = active ? j : 0;
    const float m = active ? 1.0f : 0.0f;
#pragma unroll
    for (int g = 0; g < 4; g++) {
        const int r = g * 6 + jj;          // gate row within i,f,g,o blocks
#pragma unroll
        for (int p = 0; p < 3; p++) {
            Wi[g][p] = pack2(m * wih[r * 6 + 2 * p], m * wih[r * 6 + 2 * p + 1]);
            Wh[g][p] = pack2(m * whh[r * 6 + 2 * p], m * whh[r * 6 + 2 * p + 1]);
        }
        B[g] = m * (bi[r] + bh[r]);
    }

    // ---- Recurrent state for this warp's layer
    unsigned long long hR[3] = {0ull, 0ull, 0ull};
    float c = 0.0f;

    const float2* xp = reinterpret_cast<const float2*>(x) + (size_t)b * (T_STEPS * 3);
    float* op = out + (size_t)b * (T_STEPS * 6) + j;

    // Pipeline: iteration t -> warp0 does L0(t) (t<T), warp1 does L1(t-1) (t>=1).
#pragma unroll 2
    for (int t = 0; t <= T_STEPS; t++) {
        if (warp == 0) {
            if (t < T_STEPS) {
                const float2 a0 = xp[0], a1 = xp[1], a2 = xp[2];
                xp += 3;
                unsigned long long xv[3] = { pack2(a0.x, a0.y),
                                             pack2(a1.x, a1.y),
                                             pack2(a2.x, a2.y) };
                const float h0 = cell_step(Wi, Wh, B, xv, hR, c);
                bcast8(h0, hR);
                if (active) h0buf[t & 1][bg][j] = h0;
            }
        } else {
            if (t >= 1) {
                // h0(t-1), written by warp0 in iteration t-1, fenced by the
                // __syncthreads at the end of that iteration.
                const unsigned long long* src =
                    reinterpret_cast<const unsigned long long*>(h0buf[(t - 1) & 1][bg]);
                unsigned long long xv[3] = { src[0], src[1], src[2] };
                const float h1 = cell_step(Wi, Wh, B, xv, hR, c);
                bcast8(h1, hR);
                if (active) op[(size_t)(t - 1) * 6] = h1;
            }
        }
        __syncthreads();
    }
}

extern "C" void kernel_launch(void* const* d_in, const int* in_sizes, int n_in,
                              void* d_out, int out_size) {
    const float* x    = (const float*)d_in[0];
    const float* wih0 = (const float*)d_in[1];
    const float* whh0 = (const float*)d_in[2];
    const float* bi0  = (const float*)d_in[3];
    const float* bh0  = (const float*)d_in[4];
    const float* wih1 = (const float*)d_in[5];
    const float* whh1 = (const float*)d_in[6];
    const float* bi1  = (const float*)d_in[7];
    const float* bh1  = (const float*)d_in[8];
    float* out = (float*)d_out;

    // 4096 batches / 4 per block = 1024 blocks of 64 threads (2 warps each).
    // 2048 warps total -> ~3.5 warps/SMSP, double the previous design.
    lstm2_kernel<<<1024, 64>>>(x, wih0, whh0, bi0, bh0,
                               wih1, whh1, bi1, bh1, out);
}